// round 10
// baseline (speedup 1.0000x reference)
#include <cuda_runtime.h>

// B=4096, NSPIN=2, NPS=16, D=256, NION=8, DIM=3.  8192 (b,s) pairs.
// k1: GEMM+envelope -> M (row-major [n][o]) to scratch.
// k2: warp-sync LU, 2 pairs/warp -> cofactors.

__device__ float g_M[8192 * 256];

struct __align__(16) Smem1 {
    float xs[16 * 260];      // [n][d], pitch 260, float4-aligned (16.6 KB)
    float W[256 * 16];       // [d][o] (16 KB)
    float part[8 * 256];     // [slice][n*16+o] (8 KB)
    float rs2[16 * 8 * 8];   // [n][i][c] 6 products (4 KB)
    float4 G4[128];          // [i*16+o] Gram diag+.. (2 KB)
    float2 G2[128];          // (1 KB)
    float ei[128];           // (0.5 KB)
};

__global__ void __launch_bounds__(256, 4)
k1_buildM(const float* __restrict__ eq,  const float* __restrict__ rei,
          const float* __restrict__ Wg,  const float* __restrict__ bg,
          const float* __restrict__ edg, const float* __restrict__ eig)
{
    extern __shared__ __align__(16) char smem_raw[];
    Smem1& S = *reinterpret_cast<Smem1*>(smem_raw);
    const int p = blockIdx.x, s = p & 1, t = threadIdx.x;

    // ---- Phase 0: loads (no transposes anywhere) ----
    {
        const float* xsrc = eq + (size_t)p * 4096;
        #pragma unroll
        for (int c = 0; c < 4; ++c) {
            int idx = c * 1024 + t * 4;
            float4 v = *reinterpret_cast<const float4*>(xsrc + idx);
            *reinterpret_cast<float4*>(&S.xs[(idx >> 8) * 260 + (idx & 255)]) = v;
        }
        const float* wsrc = Wg + s * 4096;          // already [d][o]
        #pragma unroll
        for (int c = 0; c < 4; ++c) {
            int idx = c * 1024 + t * 4;
            *reinterpret_cast<float4*>(&S.W[idx]) =
                *reinterpret_cast<const float4*>(wsrc + idx);
        }
        if (t < 128) {
            // rs2: (n,i) = t ; 6 pair-products of r
            const float* rp = rei + (size_t)p * 384 + t * 3;
            float r0 = rp[0], r1 = rp[1], r2 = rp[2];
            *reinterpret_cast<float4*>(&S.rs2[t * 8]) =
                make_float4(r0 * r0, r1 * r1, r2 * r2, r0 * r1);
            *reinterpret_cast<float4*>(&S.rs2[t * 8 + 4]) =
                make_float4(r0 * r2, r1 * r2, 0.f, 0.f);
            // G = A^T A for (i,o) = t of own spin
            const float* E = edg + s * 1152 + t * 9;
            float e0=E[0],e1=E[1],e2=E[2],e3=E[3],e4=E[4],e5=E[5],e6=E[6],e7=E[7],e8=E[8];
            S.G4[t] = make_float4(e0*e0 + e3*e3 + e6*e6,
                                  e1*e1 + e4*e4 + e7*e7,
                                  e2*e2 + e5*e5 + e8*e8,
                                  2.f*(e0*e1 + e3*e4 + e6*e7));
            S.G2[t] = make_float2(2.f*(e0*e2 + e3*e5 + e6*e8),
                                  2.f*(e1*e2 + e4*e5 + e7*e8));
            S.ei[t] = eig[s * 128 + t];
        }
    }
    __syncthreads();

    // ---- Phase 1: GEMM. 16 kg (16 d each) x 16 tiles (4n x 4o) ----
    const int kg = t >> 4, tl = t & 15;
    const int tn = (tl >> 2) << 2, to = (tl & 3) << 2;
    {
        float acc[4][4];
        #pragma unroll
        for (int r = 0; r < 4; ++r)
            #pragma unroll
            for (int c = 0; c < 4; ++c) acc[r][c] = 0.f;
        const int d0 = kg << 4;
        #pragma unroll
        for (int j = 0; j < 16; j += 4) {
            float4 xv[4];
            #pragma unroll
            for (int r = 0; r < 4; ++r)
                xv[r] = *reinterpret_cast<const float4*>(&S.xs[(tn + r) * 260 + d0 + j]);
            #pragma unroll
            for (int u = 0; u < 4; ++u) {
                float4 wv = *reinterpret_cast<const float4*>(&S.W[(d0 + j + u) * 16 + to]);
                #pragma unroll
                for (int r = 0; r < 4; ++r) {
                    float x = (&xv[r].x)[u];
                    acc[r][0] = fmaf(x, wv.x, acc[r][0]);
                    acc[r][1] = fmaf(x, wv.y, acc[r][1]);
                    acc[r][2] = fmaf(x, wv.z, acc[r][2]);
                    acc[r][3] = fmaf(x, wv.w, acc[r][3]);
                }
            }
        }
        const int slice = kg & 7;
        if (kg < 8) {
            #pragma unroll
            for (int r = 0; r < 4; ++r)
                *reinterpret_cast<float4*>(&S.part[slice * 256 + (tn + r) * 16 + to]) =
                    make_float4(acc[r][0], acc[r][1], acc[r][2], acc[r][3]);
        }
        __syncthreads();
        if (kg >= 8) {
            #pragma unroll
            for (int r = 0; r < 4; ++r) {
                float4* pp = reinterpret_cast<float4*>(&S.part[slice * 256 + (tn + r) * 16 + to]);
                float4 v = *pp;
                v.x += acc[r][0]; v.y += acc[r][1]; v.z += acc[r][2]; v.w += acc[r][3];
                *pp = v;
            }
        }
        __syncthreads();
    }

    // ---- Phase 2: reduce + envelope + M (row-major, coalesced STG) ----
    {
        const int n = t >> 4, o = t & 15;
        float y = bg[s * 16 + o];
        #pragma unroll
        for (int k = 0; k < 8; ++k) y += S.part[k * 256 + t];

        float env = 0.f;
        #pragma unroll
        for (int i = 0; i < 8; ++i) {
            float4 Ga = S.G4[i * 16 + o];
            float2 Gb = S.G2[i * 16 + o];
            float4 Ra = *reinterpret_cast<const float4*>(&S.rs2[(n * 8 + i) * 8]);
            float2 Rb = *reinterpret_cast<const float2*>(&S.rs2[(n * 8 + i) * 8 + 4]);
            float q = Ga.x * Ra.x;
            q = fmaf(Ga.y, Ra.y, q);
            q = fmaf(Ga.z, Ra.z, q);
            q = fmaf(Ga.w, Ra.w, q);
            q = fmaf(Gb.x, Rb.x, q);
            q = fmaf(Gb.y, Rb.y, q);
            q = fmaxf(q, 0.f);
            env = fmaf(__expf(-sqrtf(q)), S.ei[i * 16 + o], env);
        }
        g_M[(size_t)p * 256 + t] = y * env;   // M[n][o]
    }
}

// ---- k2: warp-synchronous LU + solve; 2 pairs per warp, 16 lanes each ----
__global__ void __launch_bounds__(256)
k2_solve(float* __restrict__ out)
{
    const int t = threadIdx.x;
    const int w = t >> 5, g = (t >> 4) & 1, r = t & 15;
    const int p = blockIdx.x * 16 + w * 2 + g;
    const float* Mp = &g_M[(size_t)p * 256];

    float A[16];                       // lane r: A[j] = M[j][r] (col r)
    #pragma unroll
    for (int j = 0; j < 16; ++j) A[j] = Mp[j * 16 + r];
    float m0  = Mp[r * 16];            // M[r][0]
    float rhs = (r == 0) ? 1.f : 0.f;
    int mystep = -1;
    float det = 1.f;
    unsigned remaining = 0xFFFFu, parity = 0;

    #pragma unroll
    for (int k = 0; k < 16; ++k) {
        float v = (mystep < 0) ? fabsf(A[k]) : -1.f;
        int idx = r;
        #pragma unroll
        for (int wd = 8; wd >= 1; wd >>= 1) {
            float ov = __shfl_xor_sync(0xFFFFFFFFu, v,   wd, 16);
            int   oi = __shfl_xor_sync(0xFFFFFFFFu, idx, wd, 16);
            if (ov > v || (ov == v && oi < idx)) { v = ov; idx = oi; }
        }
        const int pl = idx;
        const float pkk = __shfl_sync(0xFFFFFFFFu, A[k], pl, 16);
        det *= pkk;
        parity += __popc(remaining & ((1u << pl) - 1u));
        remaining &= ~(1u << pl);
        const bool active = (mystep < 0) && (r != pl);
        if (r == pl) mystep = k;
        const float f = __fdividef(A[k], pkk);
        #pragma unroll
        for (int j = k + 1; j < 16; ++j) {
            float pv = __shfl_sync(0xFFFFFFFFu, A[j], pl, 16);
            if (active) A[j] = fmaf(-f, pv, A[j]);
        }
        float pr = __shfl_sync(0xFFFFFFFFu, rhs, pl, 16);
        if (active) rhs = fmaf(-f, pr, rhs);
    }

    const float sdet = (parity & 1u) ? -det : det;
    float xk = 0.f;
    #pragma unroll
    for (int c = 15; c >= 0; --c) {
        unsigned b = __ballot_sync(0xFFFFFFFFu, mystep == c);
        int src = __ffs((b >> (g * 16)) & 0xFFFFu) - 1;
        float num = __shfl_sync(0xFFFFFFFFu, rhs,  src, 16);
        float den = __shfl_sync(0xFFFFFFFFu, A[c], src, 16);
        float xc  = __fdividef(num, den);
        if (r == c) xk = xc;
        if (mystep < c) rhs = fmaf(-A[c], xc, rhs);
    }
    out[(size_t)p * 16 + r] = m0 * sdet * xk;
}

extern "C" void kernel_launch(void* const* d_in, const int* in_sizes, int n_in,
                              void* d_out, int out_size) {
    const float* eq  = (const float*)d_in[0];
    const float* rei = (const float*)d_in[1];
    const float* Wg  = (const float*)d_in[2];
    const float* bg  = (const float*)d_in[3];
    const float* edg = (const float*)d_in[4];
    const float* eig = (const float*)d_in[5];
    float* out = (float*)d_out;
    const int smem = (int)sizeof(Smem1);
    cudaFuncSetAttribute(k1_buildM, cudaFuncAttributeMaxDynamicSharedMemorySize, smem);
    k1_buildM<<<8192, 256, smem>>>(eq, rei, Wg, bg, edg, eig);
    k2_solve<<<512, 256>>>(out);
}

// round 12
// speedup vs baseline: 1.5686x; 1.5686x over previous
#include <cuda_runtime.h>

// B=4096, NSPIN=2, NPS=16, D=256, NION=8, DIM=3.  8192 (b,s) pairs.
// k1: GEMM+envelope -> M^T (16x16) rows to scratch (R8 layout).
// k2: warp-sync LU with redux argmax, 2 pairs/warp.

__device__ float g_M[8192 * 256];   // M^T per pair: row o holds M[.][o]

struct __align__(16) Smem1 {
    float xs[16 * 260];      // [n][col], col = d ^ 8*((n>>2)&3) ^ 4*((d>>4)&1)
    float W[256 * 16];       // [d][o]
    float part[8 * 320];     // [slice][tl*20 + r*4 + c]
    float rs2[16 * 8 * 8];   // [n][i][c] 6 Gram products
    float4 G4[128];          // [i*16+o]
    float2 G2[128];
    float ei[128];
};

__global__ void __launch_bounds__(256, 4)
k1_buildM(const float* __restrict__ eq,  const float* __restrict__ rei,
          const float* __restrict__ Wg,  const float* __restrict__ bg,
          const float* __restrict__ edg, const float* __restrict__ eig)
{
    extern __shared__ __align__(16) char smem_raw[];
    Smem1& S = *reinterpret_cast<Smem1*>(smem_raw);
    const int p = blockIdx.x, s = p & 1, t = threadIdx.x;

    // ---- Phase 0: loads ----
    {
        const float* xsrc = eq + (size_t)p * 4096;
        #pragma unroll
        for (int c = 0; c < 4; ++c) {
            int idx = c * 1024 + t * 4;
            float4 v = *reinterpret_cast<const float4*>(xsrc + idx);
            int n = idx >> 8, dq = idx & 255;
            int col = dq ^ (((n >> 2) & 3) << 3) ^ (((dq >> 4) & 1) << 2);
            *reinterpret_cast<float4*>(&S.xs[n * 260 + col]) = v;
        }
        const float* wsrc = Wg + s * 4096;          // [d][o] direct
        #pragma unroll
        for (int c = 0; c < 4; ++c) {
            int idx = c * 1024 + t * 4;
            *reinterpret_cast<float4*>(&S.W[idx]) =
                *reinterpret_cast<const float4*>(wsrc + idx);
        }
        if (t < 128) {
            const float* rp = rei + (size_t)p * 384 + t * 3;
            float r0 = rp[0], r1 = rp[1], r2 = rp[2];
            *reinterpret_cast<float4*>(&S.rs2[t * 8]) =
                make_float4(r0 * r0, r1 * r1, r2 * r2, r0 * r1);
            *reinterpret_cast<float4*>(&S.rs2[t * 8 + 4]) =
                make_float4(r0 * r2, r1 * r2, 0.f, 0.f);
            const float* E = edg + s * 1152 + t * 9;
            float e0=E[0],e1=E[1],e2=E[2],e3=E[3],e4=E[4],e5=E[5],e6=E[6],e7=E[7],e8=E[8];
            S.G4[t] = make_float4(e0*e0 + e3*e3 + e6*e6,
                                  e1*e1 + e4*e4 + e7*e7,
                                  e2*e2 + e5*e5 + e8*e8,
                                  2.f*(e0*e1 + e3*e4 + e6*e7));
            S.G2[t] = make_float2(2.f*(e0*e2 + e3*e5 + e6*e8),
                                  2.f*(e1*e2 + e4*e5 + e7*e8));
            S.ei[t] = eig[s * 128 + t];
        }
    }
    __syncthreads();

    // ---- Phase 1: GEMM. 16 kg x 16 tiles (4n x 4o), swizzled xs ----
    const int kg = t >> 4, tl = t & 15;
    const int a  = tl >> 2;
    const int tn = a << 2, to = (tl & 3) << 2;
    {
        const int d0 = kg << 4, kb = kg & 1;
        float acc[4][4];
        #pragma unroll
        for (int r = 0; r < 4; ++r)
            #pragma unroll
            for (int c = 0; c < 4; ++c) acc[r][c] = 0.f;

        #pragma unroll
        for (int j = 0; j < 16; j += 4) {
            const int xc = (d0 + j) ^ (a << 3) ^ (kb << 2);
            float4 xv[4];
            #pragma unroll
            for (int r = 0; r < 4; ++r)
                xv[r] = *reinterpret_cast<const float4*>(&S.xs[(tn + r) * 260 + xc]);
            #pragma unroll
            for (int u = 0; u < 4; ++u) {
                float4 wv = *reinterpret_cast<const float4*>(&S.W[(d0 + j + u) * 16 + to]);
                #pragma unroll
                for (int r = 0; r < 4; ++r) {
                    float x = (&xv[r].x)[u];
                    acc[r][0] = fmaf(x, wv.x, acc[r][0]);
                    acc[r][1] = fmaf(x, wv.y, acc[r][1]);
                    acc[r][2] = fmaf(x, wv.z, acc[r][2]);
                    acc[r][3] = fmaf(x, wv.w, acc[r][3]);
                }
            }
        }
        float* pp = &S.part[(kg & 7) * 320 + tl * 20];
        if (kg < 8) {
            #pragma unroll
            for (int r = 0; r < 4; ++r)
                *reinterpret_cast<float4*>(pp + r * 4) =
                    make_float4(acc[r][0], acc[r][1], acc[r][2], acc[r][3]);
        }
        __syncthreads();
        if (kg >= 8) {
            #pragma unroll
            for (int r = 0; r < 4; ++r) {
                float4 v = *reinterpret_cast<float4*>(pp + r * 4);
                v.x += acc[r][0]; v.y += acc[r][1]; v.z += acc[r][2]; v.w += acc[r][3];
                *reinterpret_cast<float4*>(pp + r * 4) = v;
            }
        }
        __syncthreads();
    }

    // ---- Phase 2: reduce + envelope; store M^T rows (scalar STG) ----
    {
        const int n = t >> 4, o = t & 15;
        const int base = ((n >> 2) * 4 + (o >> 2)) * 20 + (n & 3) * 4 + (o & 3);
        float y = __ldg(bg + s * 16 + o);
        #pragma unroll
        for (int k = 0; k < 8; ++k) y += S.part[k * 320 + base];

        float env = 0.f;
        #pragma unroll
        for (int i = 0; i < 8; ++i) {
            float4 Ga = S.G4[i * 16 + o];
            float2 Gb = S.G2[i * 16 + o];
            float4 Ra = *reinterpret_cast<const float4*>(&S.rs2[(n * 8 + i) * 8]);
            float2 Rb = *reinterpret_cast<const float2*>(&S.rs2[(n * 8 + i) * 8 + 4]);
            float q = Ga.x * Ra.x;
            q = fmaf(Ga.y, Ra.y, q);
            q = fmaf(Ga.z, Ra.z, q);
            q = fmaf(Ga.w, Ra.w, q);
            q = fmaf(Gb.x, Rb.x, q);
            q = fmaf(Gb.y, Rb.y, q);
            q = fmaxf(q, 0.f);
            env = fmaf(__expf(-sqrtf(q)), S.ei[i * 16 + o], env);
        }
        g_M[(size_t)p * 256 + o * 16 + n] = y * env;   // M^T[o][n]
    }
}

// ---- k2: warp-sync LU + solve; 2 pairs/warp, redux argmax ----
__global__ void __launch_bounds__(256)
k2_solve(float* __restrict__ out)
{
    const int t = threadIdx.x;
    const int w = t >> 5, g = (t >> 4) & 1, lane = t & 31, r = t & 15;
    const int p = blockIdx.x * 16 + w * 2 + g;
    const float* Mp = &g_M[(size_t)p * 256];

    float A[16];                        // lane r: row r of M^T (contiguous)
    #pragma unroll
    for (int j = 0; j < 16; j += 4) {
        float4 v = *reinterpret_cast<const float4*>(Mp + r * 16 + j);
        A[j] = v.x; A[j+1] = v.y; A[j+2] = v.z; A[j+3] = v.w;
    }
    float m0  = Mp[r];                  // M^T[0][r] = M[r][0]
    float rhs = (r == 0) ? 1.f : 0.f;
    int mystep = -1;
    float det = 1.f;
    unsigned remaining = 0xFFFFu, parity = 0;
    const unsigned gmask = 0xFFFFu << ((lane >> 4) << 4);

    #pragma unroll
    for (int k = 0; k < 16; ++k) {
        unsigned key = (mystep < 0)
            ? ((__float_as_uint(fabsf(A[k])) & ~31u) | (unsigned)lane)
            : (unsigned)lane;
        unsigned mx = __reduce_max_sync(gmask, key);
        const int pl_lane = (int)(mx & 31u);     // absolute pivot lane
        const int plg = pl_lane & 15;            // within 16-group
        const float pkk = __shfl_sync(0xFFFFFFFFu, A[k], plg, 16);
        det *= pkk;
        parity += __popc(remaining & ((1u << plg) - 1u));
        remaining &= ~(1u << plg);
        const bool active = (mystep < 0) && (lane != pl_lane);
        if (lane == pl_lane) mystep = k;
        const float f = __fdividef(A[k], pkk);
        #pragma unroll
        for (int j = k + 1; j < 16; ++j) {
            float pv = __shfl_sync(0xFFFFFFFFu, A[j], plg, 16);
            if (active) A[j] = fmaf(-f, pv, A[j]);
        }
        float pr = __shfl_sync(0xFFFFFFFFu, rhs, plg, 16);
        if (active) rhs = fmaf(-f, pr, rhs);
    }

    const float sdet = (parity & 1u) ? -det : det;
    float xk = 0.f;
    #pragma unroll
    for (int c = 15; c >= 0; --c) {
        unsigned b = __ballot_sync(0xFFFFFFFFu, mystep == c);
        int src = __ffs((b >> (g * 16)) & 0xFFFFu) - 1;
        float num = __shfl_sync(0xFFFFFFFFu, rhs,  src, 16);
        float den = __shfl_sync(0xFFFFFFFFu, A[c], src, 16);
        float xc  = __fdividef(num, den);
        if (r == c) xk = xc;
        if (mystep < c) rhs = fmaf(-A[c], xc, rhs);
    }
    out[(size_t)p * 16 + r] = m0 * sdet * xk;
}

extern "C" void kernel_launch(void* const* d_in, const int* in_sizes, int n_in,
                              void* d_out, int out_size) {
    const float* eq  = (const float*)d_in[0];
    const float* rei = (const float*)d_in[1];
    const float* Wg  = (const float*)d_in[2];
    const float* bg  = (const float*)d_in[3];
    const float* edg = (const float*)d_in[4];
    const float* eig = (const float*)d_in[5];
    float* out = (float*)d_out;
    const int smem = (int)sizeof(Smem1);
    cudaFuncSetAttribute(k1_buildM, cudaFuncAttributeMaxDynamicSharedMemorySize, smem);
    k1_buildM<<<8192, 256, smem>>>(eq, rei, Wg, bg, edg, eig);
    k2_solve<<<512, 256>>>(out);
}

// round 13
// speedup vs baseline: 1.8594x; 1.1854x over previous
#include <cuda_runtime.h>

// B=4096, NSPIN=2, NPS=16, D=256, NION=8, DIM=3.  8192 (b,s) pairs.
// k1: block q handles pairs q and q+4096 (same spin). cp.async prefetch of
//     pair-2 inputs overlaps pair-1 compute. Writes M^T to scratch.
// k2: warp-sync LU with redux argmax, 2 pairs/warp.

__device__ float g_M[8192 * 256];   // M^T per pair: row o holds M[.][o]

struct __align__(16) Smem1 {
    float xs[2][16 * 260];   // [buf][n][col], col = d ^ 8*((n>>2)&3) ^ 4*((d>>4)&1)
    float W[256 * 16];       // [d][o]
    float part[8 * 320];     // [slice][tl*20 + r*4 + c]
    float rs2[16 * 8 * 8];   // [n][i][c] 6 Gram products (rebuilt per pair)
    float rsraw[384];        // prefetched rei for pair 2
    float4 G4[128];          // [i*16+o]
    float2 G2[128];
    float ei[128];
};

__device__ __forceinline__ void cp_async16(void* smem_dst, const void* gsrc) {
    unsigned sa = (unsigned)__cvta_generic_to_shared(smem_dst);
    asm volatile("cp.async.cg.shared.global [%0], [%1], 16;" :: "r"(sa), "l"(gsrc));
}

__global__ void __launch_bounds__(256, 3)
k1_buildM(const float* __restrict__ eq,  const float* __restrict__ rei,
          const float* __restrict__ Wg,  const float* __restrict__ bg,
          const float* __restrict__ edg, const float* __restrict__ eig)
{
    extern __shared__ __align__(16) char smem_raw[];
    Smem1& S = *reinterpret_cast<Smem1*>(smem_raw);
    const int q = blockIdx.x, s = q & 1, t = threadIdx.x;

    // ---- Phase 0: shared data + pair-0 inputs (plain loads) ----
    {
        const float* xsrc = eq + (size_t)q * 4096;
        #pragma unroll
        for (int c = 0; c < 4; ++c) {
            int idx = c * 1024 + t * 4;
            float4 v = *reinterpret_cast<const float4*>(xsrc + idx);
            int n = idx >> 8, dq = idx & 255;
            int col = dq ^ (((n >> 2) & 3) << 3) ^ (((dq >> 4) & 1) << 2);
            *reinterpret_cast<float4*>(&S.xs[0][n * 260 + col]) = v;
        }
        const float* wsrc = Wg + s * 4096;
        #pragma unroll
        for (int c = 0; c < 4; ++c) {
            int idx = c * 1024 + t * 4;
            *reinterpret_cast<float4*>(&S.W[idx]) =
                *reinterpret_cast<const float4*>(wsrc + idx);
        }
        if (t < 128) {
            const float* rp = rei + (size_t)q * 384 + t * 3;
            float r0 = rp[0], r1 = rp[1], r2 = rp[2];
            *reinterpret_cast<float4*>(&S.rs2[t * 8]) =
                make_float4(r0 * r0, r1 * r1, r2 * r2, r0 * r1);
            *reinterpret_cast<float4*>(&S.rs2[t * 8 + 4]) =
                make_float4(r0 * r2, r1 * r2, 0.f, 0.f);
            const float* E = edg + s * 1152 + t * 9;
            float e0=E[0],e1=E[1],e2=E[2],e3=E[3],e4=E[4],e5=E[5],e6=E[6],e7=E[7],e8=E[8];
            S.G4[t] = make_float4(e0*e0 + e3*e3 + e6*e6,
                                  e1*e1 + e4*e4 + e7*e7,
                                  e2*e2 + e5*e5 + e8*e8,
                                  2.f*(e0*e1 + e3*e4 + e6*e7));
            S.G2[t] = make_float2(2.f*(e0*e2 + e3*e5 + e6*e8),
                                  2.f*(e1*e2 + e4*e5 + e7*e8));
            S.ei[t] = eig[s * 128 + t];
        }
    }
    __syncthreads();

    // ---- Prefetch pair-1 inputs (cp.async, overlapped with pair-0 compute) ----
    {
        const size_t p1 = (size_t)q + 4096;
        const float* xsrc = eq + p1 * 4096;
        #pragma unroll
        for (int c = 0; c < 4; ++c) {
            int idx = c * 1024 + t * 4;
            int n = idx >> 8, dq = idx & 255;
            int col = dq ^ (((n >> 2) & 3) << 3) ^ (((dq >> 4) & 1) << 2);
            cp_async16(&S.xs[1][n * 260 + col], xsrc + idx);
        }
        if (t < 96)
            cp_async16(&S.rsraw[t * 4], rei + p1 * 384 + t * 4);
        asm volatile("cp.async.commit_group;");
    }

    const int kg = t >> 4, tl = t & 15;
    const int a  = tl >> 2;
    const int tn = a << 2, to = (tl & 3) << 2;
    const float bias = __ldg(bg + s * 16 + (t & 15));

    #pragma unroll
    for (int it = 0; it < 2; ++it) {
        const size_t p = (size_t)q + (it ? 4096 : 0);
        if (it == 1) {
            asm volatile("cp.async.wait_group 0;");
            __syncthreads();                    // xs[1]/rsraw ready; part reads of it0 done
            if (t < 128) {                      // rebuild rs2 for pair 1
                float r0 = S.rsraw[t*3], r1 = S.rsraw[t*3+1], r2 = S.rsraw[t*3+2];
                *reinterpret_cast<float4*>(&S.rs2[t * 8]) =
                    make_float4(r0 * r0, r1 * r1, r2 * r2, r0 * r1);
                *reinterpret_cast<float4*>(&S.rs2[t * 8 + 4]) =
                    make_float4(r0 * r2, r1 * r2, 0.f, 0.f);
            }
        }

        // ---- GEMM. 16 kg x 16 tiles (4n x 4o), swizzled xs ----
        {
            const int d0 = kg << 4, kb = kg & 1;
            float acc[4][4];
            #pragma unroll
            for (int r = 0; r < 4; ++r)
                #pragma unroll
                for (int c = 0; c < 4; ++c) acc[r][c] = 0.f;

            #pragma unroll
            for (int j = 0; j < 16; j += 4) {
                const int xc = (d0 + j) ^ (a << 3) ^ (kb << 2);
                float4 xv[4];
                #pragma unroll
                for (int r = 0; r < 4; ++r)
                    xv[r] = *reinterpret_cast<const float4*>(&S.xs[it][(tn + r) * 260 + xc]);
                #pragma unroll
                for (int u = 0; u < 4; ++u) {
                    float4 wv = *reinterpret_cast<const float4*>(&S.W[(d0 + j + u) * 16 + to]);
                    #pragma unroll
                    for (int r = 0; r < 4; ++r) {
                        float x = (&xv[r].x)[u];
                        acc[r][0] = fmaf(x, wv.x, acc[r][0]);
                        acc[r][1] = fmaf(x, wv.y, acc[r][1]);
                        acc[r][2] = fmaf(x, wv.z, acc[r][2]);
                        acc[r][3] = fmaf(x, wv.w, acc[r][3]);
                    }
                }
            }
            float* pp = &S.part[(kg & 7) * 320 + tl * 20];
            if (kg < 8) {
                #pragma unroll
                for (int r = 0; r < 4; ++r)
                    *reinterpret_cast<float4*>(pp + r * 4) =
                        make_float4(acc[r][0], acc[r][1], acc[r][2], acc[r][3]);
            }
            __syncthreads();
            if (kg >= 8) {
                #pragma unroll
                for (int r = 0; r < 4; ++r) {
                    float4 v = *reinterpret_cast<float4*>(pp + r * 4);
                    v.x += acc[r][0]; v.y += acc[r][1]; v.z += acc[r][2]; v.w += acc[r][3];
                    *reinterpret_cast<float4*>(pp + r * 4) = v;
                }
            }
            __syncthreads();
        }

        // ---- reduce + envelope; store M^T rows ----
        {
            const int n = t >> 4, o = t & 15;
            const int base = ((n >> 2) * 4 + (o >> 2)) * 20 + (n & 3) * 4 + (o & 3);
            float y = bias;
            #pragma unroll
            for (int k = 0; k < 8; ++k) y += S.part[k * 320 + base];

            float env = 0.f;
            #pragma unroll
            for (int i = 0; i < 8; ++i) {
                float4 Ga = S.G4[i * 16 + o];
                float2 Gb = S.G2[i * 16 + o];
                float4 Ra = *reinterpret_cast<const float4*>(&S.rs2[(n * 8 + i) * 8]);
                float2 Rb = *reinterpret_cast<const float2*>(&S.rs2[(n * 8 + i) * 8 + 4]);
                float qv = Ga.x * Ra.x;
                qv = fmaf(Ga.y, Ra.y, qv);
                qv = fmaf(Ga.z, Ra.z, qv);
                qv = fmaf(Ga.w, Ra.w, qv);
                qv = fmaf(Gb.x, Rb.x, qv);
                qv = fmaf(Gb.y, Rb.y, qv);
                qv = fmaxf(qv, 0.f);
                env = fmaf(__expf(-sqrtf(qv)), S.ei[i * 16 + o], env);
            }
            g_M[p * 256 + o * 16 + n] = y * env;   // M^T[o][n]
        }
    }
}

// ---- k2: warp-sync LU + solve; 2 pairs/warp, redux argmax ----
__global__ void __launch_bounds__(256)
k2_solve(float* __restrict__ out)
{
    const int t = threadIdx.x;
    const int w = t >> 5, g = (t >> 4) & 1, lane = t & 31, r = t & 15;
    const int p = blockIdx.x * 16 + w * 2 + g;
    const float* Mp = &g_M[(size_t)p * 256];

    float A[16];
    #pragma unroll
    for (int j = 0; j < 16; j += 4) {
        float4 v = *reinterpret_cast<const float4*>(Mp + r * 16 + j);
        A[j] = v.x; A[j+1] = v.y; A[j+2] = v.z; A[j+3] = v.w;
    }
    float m0  = Mp[r];
    float rhs = (r == 0) ? 1.f : 0.f;
    int mystep = -1;
    float det = 1.f;
    unsigned remaining = 0xFFFFu, parity = 0;
    const unsigned gmask = 0xFFFFu << ((lane >> 4) << 4);

    #pragma unroll
    for (int k = 0; k < 16; ++k) {
        unsigned key = (mystep < 0)
            ? ((__float_as_uint(fabsf(A[k])) & ~31u) | (unsigned)lane)
            : (unsigned)lane;
        unsigned mx = __reduce_max_sync(gmask, key);
        const int pl_lane = (int)(mx & 31u);
        const int plg = pl_lane & 15;
        const float pkk = __shfl_sync(0xFFFFFFFFu, A[k], plg, 16);
        det *= pkk;
        parity += __popc(remaining & ((1u << plg) - 1u));
        remaining &= ~(1u << plg);
        const bool active = (mystep < 0) && (lane != pl_lane);
        if (lane == pl_lane) mystep = k;
        const float f = __fdividef(A[k], pkk);
        #pragma unroll
        for (int j = k + 1; j < 16; ++j) {
            float pv = __shfl_sync(0xFFFFFFFFu, A[j], plg, 16);
            if (active) A[j] = fmaf(-f, pv, A[j]);
        }
        float pr = __shfl_sync(0xFFFFFFFFu, rhs, plg, 16);
        if (active) rhs = fmaf(-f, pr, rhs);
    }

    const float sdet = (parity & 1u) ? -det : det;
    float xk = 0.f;
    #pragma unroll
    for (int c = 15; c >= 0; --c) {
        unsigned b = __ballot_sync(0xFFFFFFFFu, mystep == c);
        int src = __ffs((b >> (g * 16)) & 0xFFFFu) - 1;
        float num = __shfl_sync(0xFFFFFFFFu, rhs,  src, 16);
        float den = __shfl_sync(0xFFFFFFFFu, A[c], src, 16);
        float xc  = __fdividef(num, den);
        if (r == c) xk = xc;
        if (mystep < c) rhs = fmaf(-A[c], xc, rhs);
    }
    out[(size_t)p * 16 + r] = m0 * sdet * xk;
}

extern "C" void kernel_launch(void* const* d_in, const int* in_sizes, int n_in,
                              void* d_out, int out_size) {
    const float* eq  = (const float*)d_in[0];
    const float* rei = (const float*)d_in[1];
    const float* Wg  = (const float*)d_in[2];
    const float* bg  = (const float*)d_in[3];
    const float* edg = (const float*)d_in[4];
    const float* eig = (const float*)d_in[5];
    float* out = (float*)d_out;
    const int smem = (int)sizeof(Smem1);
    cudaFuncSetAttribute(k1_buildM, cudaFuncAttributeMaxDynamicSharedMemorySize, smem);
    k1_buildM<<<4096, 256, smem>>>(eq, rei, Wg, bg, edg, eig);
    k2_solve<<<512, 256>>>(out);
}

// round 14
// speedup vs baseline: 1.9593x; 1.0537x over previous
#include <cuda_runtime.h>

// B=4096, NSPIN=2, NPS=16, D=256, NION=8, DIM=3.  8192 (b,s) pairs.
// k1: 456 persistent blocks (152 SM x 3). Block b owns pairs b+456j (spin b&1).
//     Depth-2 cp.async pipeline; W/G/ei loaded once. Writes M^T to scratch.
// k2: warp-sync LU with redux argmax, 2 pairs/warp.

#define NBLK 456

__device__ float g_M[8192 * 256];   // M^T per pair: row o holds M[.][o]

struct __align__(16) Smem1 {
    float xs[2][16 * 260];   // [buf][n][col], col = d ^ 8*((n>>2)&3) ^ 4*((d>>4)&1)
    float W[256 * 16];       // [d][o]
    float part[8 * 320];     // [slice][tl*20 + r*4 + c]
    float rs2[16 * 8 * 8];   // [n][i][c] 6 Gram products (rebuilt per pair)
    float rsraw[2][384];     // [buf] raw rei
    float4 G4[128];          // [i*16+o]
    float2 G2[128];
    float ei[128];
};

__device__ __forceinline__ void cp_async16(void* smem_dst, const void* gsrc) {
    unsigned sa = (unsigned)__cvta_generic_to_shared(smem_dst);
    asm volatile("cp.async.cg.shared.global [%0], [%1], 16;" :: "r"(sa), "l"(gsrc));
}

__device__ __forceinline__ void prefetch_pair(Smem1& S, int buf,
                                              const float* __restrict__ eq,
                                              const float* __restrict__ rei,
                                              size_t p, int t) {
    const float* xsrc = eq + p * 4096;
    #pragma unroll
    for (int c = 0; c < 4; ++c) {
        int idx = c * 1024 + t * 4;
        int n = idx >> 8, dq = idx & 255;
        int col = dq ^ (((n >> 2) & 3) << 3) ^ (((dq >> 4) & 1) << 2);
        cp_async16(&S.xs[buf][n * 260 + col], xsrc + idx);
    }
    if (t < 96)
        cp_async16(&S.rsraw[buf][t * 4], rei + p * 384 + t * 4);
    asm volatile("cp.async.commit_group;");
}

__global__ void __launch_bounds__(256, 3)
k1_buildM(const float* __restrict__ eq,  const float* __restrict__ rei,
          const float* __restrict__ Wg,  const float* __restrict__ bg,
          const float* __restrict__ edg, const float* __restrict__ eig)
{
    extern __shared__ __align__(16) char smem_raw[];
    Smem1& S = *reinterpret_cast<Smem1*>(smem_raw);
    const int b = blockIdx.x, s = b & 1, t = threadIdx.x;
    const int cnt = (8192 - b + NBLK - 1) / NBLK;   // pairs this block owns

    // ---- Prologue: prefetch pairs 0,1; load shared data once ----
    prefetch_pair(S, 0, eq, rei, (size_t)b, t);
    if (cnt > 1) prefetch_pair(S, 1, eq, rei, (size_t)b + NBLK, t);
    {
        const float* wsrc = Wg + s * 4096;
        #pragma unroll
        for (int c = 0; c < 4; ++c) {
            int idx = c * 1024 + t * 4;
            *reinterpret_cast<float4*>(&S.W[idx]) =
                *reinterpret_cast<const float4*>(wsrc + idx);
        }
        if (t < 128) {
            const float* E = edg + s * 1152 + t * 9;
            float e0=E[0],e1=E[1],e2=E[2],e3=E[3],e4=E[4],e5=E[5],e6=E[6],e7=E[7],e8=E[8];
            S.G4[t] = make_float4(e0*e0 + e3*e3 + e6*e6,
                                  e1*e1 + e4*e4 + e7*e7,
                                  e2*e2 + e5*e5 + e8*e8,
                                  2.f*(e0*e1 + e3*e4 + e6*e7));
            S.G2[t] = make_float2(2.f*(e0*e2 + e3*e5 + e6*e8),
                                  2.f*(e1*e2 + e4*e5 + e7*e8));
            S.ei[t] = eig[s * 128 + t];
        }
    }

    const int kg = t >> 4, tl = t & 15;
    const int a  = tl >> 2;
    const int tn = a << 2, to = (tl & 3) << 2;
    const float bias = __ldg(bg + s * 16 + (t & 15));

    for (int j = 0; j < cnt; ++j) {
        const int buf = j & 1;
        const size_t p = (size_t)b + (size_t)j * NBLK;

        asm volatile("cp.async.wait_group 1;");   // pair j arrived
        __syncthreads();                          // visible to all; prev iter done

        if (t < 128) {                            // rs2 for this pair
            const float* rr = &S.rsraw[buf][t * 3];
            float r0 = rr[0], r1 = rr[1], r2 = rr[2];
            *reinterpret_cast<float4*>(&S.rs2[t * 8]) =
                make_float4(r0 * r0, r1 * r1, r2 * r2, r0 * r1);
            *reinterpret_cast<float4*>(&S.rs2[t * 8 + 4]) =
                make_float4(r0 * r2, r1 * r2, 0.f, 0.f);
        }

        // ---- GEMM. 16 kg x 16 tiles (4n x 4o), swizzled xs ----
        {
            const int d0 = kg << 4, kb = kg & 1;
            float acc[4][4];
            #pragma unroll
            for (int r = 0; r < 4; ++r)
                #pragma unroll
                for (int c = 0; c < 4; ++c) acc[r][c] = 0.f;

            #pragma unroll
            for (int jj = 0; jj < 16; jj += 4) {
                const int xc = (d0 + jj) ^ (a << 3) ^ (kb << 2);
                float4 xv[4];
                #pragma unroll
                for (int r = 0; r < 4; ++r)
                    xv[r] = *reinterpret_cast<const float4*>(&S.xs[buf][(tn + r) * 260 + xc]);
                #pragma unroll
                for (int u = 0; u < 4; ++u) {
                    float4 wv = *reinterpret_cast<const float4*>(&S.W[(d0 + jj + u) * 16 + to]);
                    #pragma unroll
                    for (int r = 0; r < 4; ++r) {
                        float x = (&xv[r].x)[u];
                        acc[r][0] = fmaf(x, wv.x, acc[r][0]);
                        acc[r][1] = fmaf(x, wv.y, acc[r][1]);
                        acc[r][2] = fmaf(x, wv.z, acc[r][2]);
                        acc[r][3] = fmaf(x, wv.w, acc[r][3]);
                    }
                }
            }
            float* pp = &S.part[(kg & 7) * 320 + tl * 20];
            if (kg < 8) {
                #pragma unroll
                for (int r = 0; r < 4; ++r)
                    *reinterpret_cast<float4*>(pp + r * 4) =
                        make_float4(acc[r][0], acc[r][1], acc[r][2], acc[r][3]);
            }
            __syncthreads();
            if (kg >= 8) {
                #pragma unroll
                for (int r = 0; r < 4; ++r) {
                    float4 v = *reinterpret_cast<float4*>(pp + r * 4);
                    v.x += acc[r][0]; v.y += acc[r][1]; v.z += acc[r][2]; v.w += acc[r][3];
                    *reinterpret_cast<float4*>(pp + r * 4) = v;
                }
            }
            __syncthreads();
        }

        // xs[buf] fully consumed (reads ended before first sync) -> refill it
        if (j + 2 < cnt)
            prefetch_pair(S, buf, eq, rei, p + 2 * NBLK, t);

        // ---- reduce + envelope; store M^T rows ----
        {
            const int n = t >> 4, o = t & 15;
            const int base = ((n >> 2) * 4 + (o >> 2)) * 20 + (n & 3) * 4 + (o & 3);
            float y = bias;
            #pragma unroll
            for (int k = 0; k < 8; ++k) y += S.part[k * 320 + base];

            float env = 0.f;
            #pragma unroll
            for (int i = 0; i < 8; ++i) {
                float4 Ga = S.G4[i * 16 + o];
                float2 Gb = S.G2[i * 16 + o];
                float4 Ra = *reinterpret_cast<const float4*>(&S.rs2[(n * 8 + i) * 8]);
                float2 Rb = *reinterpret_cast<const float2*>(&S.rs2[(n * 8 + i) * 8 + 4]);
                float qv = Ga.x * Ra.x;
                qv = fmaf(Ga.y, Ra.y, qv);
                qv = fmaf(Ga.z, Ra.z, qv);
                qv = fmaf(Ga.w, Ra.w, qv);
                qv = fmaf(Gb.x, Rb.x, qv);
                qv = fmaf(Gb.y, Rb.y, qv);
                qv = fmaxf(qv, 0.f);
                env = fmaf(__expf(-sqrtf(qv)), S.ei[i * 16 + o], env);
            }
            g_M[p * 256 + o * 16 + n] = y * env;   // M^T[o][n]
        }
    }
}

// ---- k2: warp-sync LU + solve; 2 pairs/warp, redux argmax ----
__global__ void __launch_bounds__(256)
k2_solve(float* __restrict__ out)
{
    const int t = threadIdx.x;
    const int w = t >> 5, g = (t >> 4) & 1, lane = t & 31, r = t & 15;
    const int p = blockIdx.x * 16 + w * 2 + g;
    const float* Mp = &g_M[(size_t)p * 256];

    float A[16];
    #pragma unroll
    for (int j = 0; j < 16; j += 4) {
        float4 v = *reinterpret_cast<const float4*>(Mp + r * 16 + j);
        A[j] = v.x; A[j+1] = v.y; A[j+2] = v.z; A[j+3] = v.w;
    }
    float m0  = Mp[r];
    float rhs = (r == 0) ? 1.f : 0.f;
    int mystep = -1;
    float det = 1.f;
    unsigned remaining = 0xFFFFu, parity = 0;
    const unsigned gmask = 0xFFFFu << ((lane >> 4) << 4);

    #pragma unroll
    for (int k = 0; k < 16; ++k) {
        unsigned key = (mystep < 0)
            ? ((__float_as_uint(fabsf(A[k])) & ~31u) | (unsigned)lane)
            : (unsigned)lane;
        unsigned mx = __reduce_max_sync(gmask, key);
        const int pl_lane = (int)(mx & 31u);
        const int plg = pl_lane & 15;
        const float pkk = __shfl_sync(0xFFFFFFFFu, A[k], plg, 16);
        det *= pkk;
        parity += __popc(remaining & ((1u << plg) - 1u));
        remaining &= ~(1u << plg);
        const bool active = (mystep < 0) && (lane != pl_lane);
        if (lane == pl_lane) mystep = k;
        const float f = __fdividef(A[k], pkk);
        #pragma unroll
        for (int j = k + 1; j < 16; ++j) {
            float pv = __shfl_sync(0xFFFFFFFFu, A[j], plg, 16);
            if (active) A[j] = fmaf(-f, pv, A[j]);
        }
        float pr = __shfl_sync(0xFFFFFFFFu, rhs, plg, 16);
        if (active) rhs = fmaf(-f, pr, rhs);
    }

    const float sdet = (parity & 1u) ? -det : det;
    float xk = 0.f;
    #pragma unroll
    for (int c = 15; c >= 0; --c) {
        unsigned bb = __ballot_sync(0xFFFFFFFFu, mystep == c);
        int src = __ffs((bb >> (g * 16)) & 0xFFFFu) - 1;
        float num = __shfl_sync(0xFFFFFFFFu, rhs,  src, 16);
        float den = __shfl_sync(0xFFFFFFFFu, A[c], src, 16);
        float xc  = __fdividef(num, den);
        if (r == c) xk = xc;
        if (mystep < c) rhs = fmaf(-A[c], xc, rhs);
    }
    out[(size_t)p * 16 + r] = m0 * sdet * xk;
}

extern "C" void kernel_launch(void* const* d_in, const int* in_sizes, int n_in,
                              void* d_out, int out_size) {
    const float* eq  = (const float*)d_in[0];
    const float* rei = (const float*)d_in[1];
    const float* Wg  = (const float*)d_in[2];
    const float* bg  = (const float*)d_in[3];
    const float* edg = (const float*)d_in[4];
    const float* eig = (const float*)d_in[5];
    float* out = (float*)d_out;
    const int smem = (int)sizeof(Smem1);
    cudaFuncSetAttribute(k1_buildM, cudaFuncAttributeMaxDynamicSharedMemorySize, smem);
    k1_buildM<<<NBLK, 256, smem>>>(eq, rei, Wg, bg, edg, eig);
    k2_solve<<<512, 256>>>(out);
}

// round 16
// speedup vs baseline: 2.0417x; 1.0421x over previous
#include <cuda_runtime.h>

// B=4096, NSPIN=2, NPS=16, D=256, NION=8, DIM=3.  8192 (b,s) pairs.
// k1: 456 persistent blocks; depth-2 cp.async pipeline; bank-padded W.
// k2: warp-sync LU, TWO pairs per 16-lane group (ILP), redux argmax.

#define NBLK 456

__device__ float g_M[8192 * 256];   // M^T per pair: row o holds M[.][o]

struct __align__(16) Smem1 {
    float xs[2][16 * 260];   // [buf][n][col], col = d ^ 8*((n>>2)&3) ^ 4*((d>>4)&1)
    float W[16 * 272];       // [kgb][dlow][o], stride 272 (bank shift 16)
    float part[8 * 320];     // [slice][tl*20 + r*4 + c]
    float rs2[16 * 8 * 8];   // [n][i][c]
    float rsraw[2][384];
    float4 G4[128];
    float2 G2[128];
    float ei[128];
};

__device__ __forceinline__ void cp_async16(void* smem_dst, const void* gsrc) {
    unsigned sa = (unsigned)__cvta_generic_to_shared(smem_dst);
    asm volatile("cp.async.cg.shared.global [%0], [%1], 16;" :: "r"(sa), "l"(gsrc));
}

__device__ __forceinline__ void prefetch_pair(Smem1& S, int buf,
                                              const float* __restrict__ eq,
                                              const float* __restrict__ rei,
                                              size_t p, int t) {
    const float* xsrc = eq + p * 4096;
    #pragma unroll
    for (int c = 0; c < 4; ++c) {
        int idx = c * 1024 + t * 4;
        int n = idx >> 8, dq = idx & 255;
        int col = dq ^ (((n >> 2) & 3) << 3) ^ (((dq >> 4) & 1) << 2);
        cp_async16(&S.xs[buf][n * 260 + col], xsrc + idx);
    }
    if (t < 96)
        cp_async16(&S.rsraw[buf][t * 4], rei + p * 384 + t * 4);
    asm volatile("cp.async.commit_group;");
}

__global__ void __launch_bounds__(256, 3)
k1_buildM(const float* __restrict__ eq,  const float* __restrict__ rei,
          const float* __restrict__ Wg,  const float* __restrict__ bg,
          const float* __restrict__ edg, const float* __restrict__ eig)
{
    extern __shared__ __align__(16) char smem_raw[];
    Smem1& S = *reinterpret_cast<Smem1*>(smem_raw);
    const int b = blockIdx.x, s = b & 1, t = threadIdx.x;
    const int cnt = (8192 - b + NBLK - 1) / NBLK;

    prefetch_pair(S, 0, eq, rei, (size_t)b, t);
    if (cnt > 1) prefetch_pair(S, 1, eq, rei, (size_t)b + NBLK, t);
    {
        const float* wsrc = Wg + s * 4096;
        #pragma unroll
        for (int c = 0; c < 4; ++c) {
            int idx = c * 1024 + t * 4;         // = d*16 + o(4-aligned)
            int d = idx >> 4, o = idx & 15;
            *reinterpret_cast<float4*>(&S.W[(d >> 4) * 272 + (d & 15) * 16 + o]) =
                *reinterpret_cast<const float4*>(wsrc + idx);
        }
        if (t < 128) {
            const float* E = edg + s * 1152 + t * 9;
            float e0=E[0],e1=E[1],e2=E[2],e3=E[3],e4=E[4],e5=E[5],e6=E[6],e7=E[7],e8=E[8];
            S.G4[t] = make_float4(e0*e0 + e3*e3 + e6*e6,
                                  e1*e1 + e4*e4 + e7*e7,
                                  e2*e2 + e5*e5 + e8*e8,
                                  2.f*(e0*e1 + e3*e4 + e6*e7));
            S.G2[t] = make_float2(2.f*(e0*e2 + e3*e5 + e6*e8),
                                  2.f*(e1*e2 + e4*e5 + e7*e8));
            S.ei[t] = eig[s * 128 + t];
        }
    }

    const int kg = t >> 4, tl = t & 15;
    const int a  = tl >> 2;
    const int tn = a << 2, to = (tl & 3) << 2;
    const int wbase = kg * 272 + to;
    const float bias = __ldg(bg + s * 16 + (t & 15));

    for (int j = 0; j < cnt; ++j) {
        const int buf = j & 1;
        const size_t p = (size_t)b + (size_t)j * NBLK;

        asm volatile("cp.async.wait_group 1;");
        __syncthreads();

        if (t < 128) {
            const float* rr = &S.rsraw[buf][t * 3];
            float r0 = rr[0], r1 = rr[1], r2 = rr[2];
            *reinterpret_cast<float4*>(&S.rs2[t * 8]) =
                make_float4(r0 * r0, r1 * r1, r2 * r2, r0 * r1);
            *reinterpret_cast<float4*>(&S.rs2[t * 8 + 4]) =
                make_float4(r0 * r2, r1 * r2, 0.f, 0.f);
        }

        // ---- GEMM: 16 kg x 16 tiles (4n x 4o); xs swizzled, W padded ----
        {
            const int d0 = kg << 4, kb = kg & 1;
            float acc[4][4];
            #pragma unroll
            for (int r = 0; r < 4; ++r)
                #pragma unroll
                for (int c = 0; c < 4; ++c) acc[r][c] = 0.f;

            #pragma unroll
            for (int jj = 0; jj < 16; jj += 4) {
                const int xc = (d0 + jj) ^ (a << 3) ^ (kb << 2);
                float4 xv[4];
                #pragma unroll
                for (int r = 0; r < 4; ++r)
                    xv[r] = *reinterpret_cast<const float4*>(&S.xs[buf][(tn + r) * 260 + xc]);
                #pragma unroll
                for (int u = 0; u < 4; ++u) {
                    float4 wv = *reinterpret_cast<const float4*>(&S.W[wbase + (jj + u) * 16]);
                    #pragma unroll
                    for (int r = 0; r < 4; ++r) {
                        float x = (&xv[r].x)[u];
                        acc[r][0] = fmaf(x, wv.x, acc[r][0]);
                        acc[r][1] = fmaf(x, wv.y, acc[r][1]);
                        acc[r][2] = fmaf(x, wv.z, acc[r][2]);
                        acc[r][3] = fmaf(x, wv.w, acc[r][3]);
                    }
                }
            }
            float* pp = &S.part[(kg & 7) * 320 + tl * 20];
            if (kg < 8) {
                #pragma unroll
                for (int r = 0; r < 4; ++r)
                    *reinterpret_cast<float4*>(pp + r * 4) =
                        make_float4(acc[r][0], acc[r][1], acc[r][2], acc[r][3]);
            }
            __syncthreads();
            if (kg >= 8) {
                #pragma unroll
                for (int r = 0; r < 4; ++r) {
                    float4 v = *reinterpret_cast<float4*>(pp + r * 4);
                    v.x += acc[r][0]; v.y += acc[r][1]; v.z += acc[r][2]; v.w += acc[r][3];
                    *reinterpret_cast<float4*>(pp + r * 4) = v;
                }
            }
            __syncthreads();
        }

        if (j + 2 < cnt)
            prefetch_pair(S, buf, eq, rei, p + 2 * NBLK, t);

        // ---- reduce + envelope; store M^T ----
        {
            const int n = t >> 4, o = t & 15;
            const int base = ((n >> 2) * 4 + (o >> 2)) * 20 + (n & 3) * 4 + (o & 3);
            float y = bias;
            #pragma unroll
            for (int k = 0; k < 8; ++k) y += S.part[k * 320 + base];

            float env = 0.f;
            #pragma unroll
            for (int i = 0; i < 8; ++i) {
                float4 Ga = S.G4[i * 16 + o];
                float2 Gb = S.G2[i * 16 + o];
                float4 Ra = *reinterpret_cast<const float4*>(&S.rs2[(n * 8 + i) * 8]);
                float2 Rb = *reinterpret_cast<const float2*>(&S.rs2[(n * 8 + i) * 8 + 4]);
                float qv = Ga.x * Ra.x;
                qv = fmaf(Ga.y, Ra.y, qv);
                qv = fmaf(Ga.z, Ra.z, qv);
                qv = fmaf(Ga.w, Ra.w, qv);
                qv = fmaf(Gb.x, Rb.x, qv);
                qv = fmaf(Gb.y, Rb.y, qv);
                qv = fmaxf(qv, 0.f);
                env = fmaf(__expf(-sqrtf(qv)), S.ei[i * 16 + o], env);
            }
            g_M[p * 256 + o * 16 + n] = y * env;
        }
    }
}

// ---- k2: dual-pair warp-sync LU (ILP x2); 16-lane groups, redux argmax ----
__global__ void __launch_bounds__(256)
k2_solve(float* __restrict__ out)
{
    const int t = threadIdx.x;
    const int w = t >> 5, g = (t >> 4) & 1, lane = t & 31, r = t & 15;
    const int slot = blockIdx.x * 16 + w * 2 + g;    // 256 blocks -> 4096 slots
    const int pA = slot, pB = slot + 4096;
    const float* MA = &g_M[(size_t)pA * 256];
    const float* MB = &g_M[(size_t)pB * 256];

    float A[16], B[16];
    #pragma unroll
    for (int j = 0; j < 16; j += 4) {
        float4 va = *reinterpret_cast<const float4*>(MA + r * 16 + j);
        float4 vb = *reinterpret_cast<const float4*>(MB + r * 16 + j);
        A[j]=va.x; A[j+1]=va.y; A[j+2]=va.z; A[j+3]=va.w;
        B[j]=vb.x; B[j+1]=vb.y; B[j+2]=vb.z; B[j+3]=vb.w;
    }
    float m0A = MA[r], m0B = MB[r];
    float rhsA = (r == 0) ? 1.f : 0.f, rhsB = rhsA;
    int msA = -1, msB = -1;
    float detA = 1.f, detB = 1.f;
    unsigned remA = 0xFFFFu, remB = 0xFFFFu, parA = 0, parB = 0;
    const unsigned gmask = 0xFFFFu << ((lane >> 4) << 4);

    #pragma unroll
    for (int k = 0; k < 16; ++k) {
        unsigned keyA = (msA < 0)
            ? ((__float_as_uint(fabsf(A[k])) & ~31u) | (unsigned)lane) : (unsigned)lane;
        unsigned keyB = (msB < 0)
            ? ((__float_as_uint(fabsf(B[k])) & ~31u) | (unsigned)lane) : (unsigned)lane;
        unsigned mxA = __reduce_max_sync(gmask, keyA);
        unsigned mxB = __reduce_max_sync(gmask, keyB);
        const int plA = (int)(mxA & 31u), plB = (int)(mxB & 31u);
        const int pgA = plA & 15,          pgB = plB & 15;
        const float pkA = __shfl_sync(0xFFFFFFFFu, A[k], pgA, 16);
        const float pkB = __shfl_sync(0xFFFFFFFFu, B[k], pgB, 16);
        detA *= pkA; detB *= pkB;
        parA += __popc(remA & ((1u << pgA) - 1u)); remA &= ~(1u << pgA);
        parB += __popc(remB & ((1u << pgB) - 1u)); remB &= ~(1u << pgB);
        const bool acA = (msA < 0) && (lane != plA);
        const bool acB = (msB < 0) && (lane != plB);
        if (lane == plA) msA = k;
        if (lane == plB) msB = k;
        const float fA = __fdividef(A[k], pkA);
        const float fB = __fdividef(B[k], pkB);
        #pragma unroll
        for (int j = k + 1; j < 16; ++j) {
            float pvA = __shfl_sync(0xFFFFFFFFu, A[j], pgA, 16);
            float pvB = __shfl_sync(0xFFFFFFFFu, B[j], pgB, 16);
            if (acA) A[j] = fmaf(-fA, pvA, A[j]);
            if (acB) B[j] = fmaf(-fB, pvB, B[j]);
        }
        float prA = __shfl_sync(0xFFFFFFFFu, rhsA, pgA, 16);
        float prB = __shfl_sync(0xFFFFFFFFu, rhsB, pgB, 16);
        if (acA) rhsA = fmaf(-fA, prA, rhsA);
        if (acB) rhsB = fmaf(-fB, prB, rhsB);
    }

    const float sdA = (parA & 1u) ? -detA : detA;
    const float sdB = (parB & 1u) ? -detB : detB;
    float xkA = 0.f, xkB = 0.f;
    #pragma unroll
    for (int c = 15; c >= 0; --c) {
        unsigned bA = __ballot_sync(0xFFFFFFFFu, msA == c);
        unsigned bB = __ballot_sync(0xFFFFFFFFu, msB == c);
        int sA = __ffs((bA >> (g * 16)) & 0xFFFFu) - 1;
        int sB = __ffs((bB >> (g * 16)) & 0xFFFFu) - 1;
        float nA = __shfl_sync(0xFFFFFFFFu, rhsA, sA, 16);
        float dA = __shfl_sync(0xFFFFFFFFu, A[c], sA, 16);
        float nB = __shfl_sync(0xFFFFFFFFu, rhsB, sB, 16);
        float dB = __shfl_sync(0xFFFFFFFFu, B[c], sB, 16);
        float xcA = __fdividef(nA, dA);
        float xcB = __fdividef(nB, dB);
        if (r == c) { xkA = xcA; xkB = xcB; }
        if (msA < c) rhsA = fmaf(-A[c], xcA, rhsA);
        if (msB < c) rhsB = fmaf(-B[c], xcB, rhsB);
    }
    out[(size_t)pA * 16 + r] = m0A * sdA * xkA;
    out[(size_t)pB * 16 + r] = m0B * sdB * xkB;
}

extern "C" void kernel_launch(void* const* d_in, const int* in_sizes, int n_in,
                              void* d_out, int out_size) {
    const float* eq  = (const float*)d_in[0];
    const float* rei = (const float*)d_in[1];
    const float* Wg  = (const float*)d_in[2];
    const float* bg  = (const float*)d_in[3];
    const float* edg = (const float*)d_in[4];
    const float* eig = (const float*)d_in[5];
    float* out = (float*)d_out;
    const int smem = (int)sizeof(Smem1);
    cudaFuncSetAttribute(k1_buildM, cudaFuncAttributeMaxDynamicSharedMemorySize, smem);
    k1_buildM<<<NBLK, 256, smem>>>(eq, rei, Wg, bg, edg, eig);
    k2_solve<<<256, 256>>>(out);
}